// round 1
// baseline (speedup 1.0000x reference)
#include <cuda_runtime.h>

// Problem constants (fixed shapes for this problem instance)
#define N_CELL   66
#define N_NODES  30000
#define FDIM     256
#define E_TOT    960000            // directed edges (both directions)
#define NF       (N_NODES * FDIM)  // 7,680,000
#define NF4      (NF / 4)
#define CELL4    ((N_CELL * FDIM) / 4)
#define NB_STAT  125
#define ROWS_PER 240               // 125 * 240 = 30000
#define BN_EPS   1e-5f

// ---------------- device scratch (static, no allocation) ----------------
__device__ float g_x0[NF];
__device__ float g_x1[NF];
__device__ float g_deg[N_NODES];
__device__ float g_dinv[N_NODES];
__device__ int   g_count[N_NODES];
__device__ int   g_colptr[N_NODES + 1];
__device__ int   g_cursor[N_NODES];
__device__ int   g_erow[E_TOT];
__device__ float g_enorm[E_TOT];
__device__ float g_part1[NB_STAT * FDIM];
__device__ float g_part2[NB_STAT * FDIM];
__device__ float g_scale[FDIM];
__device__ float g_shift[FDIM];

// ---------------- setup kernels ----------------
__global__ void k_init() {
    int i = blockIdx.x * blockDim.x + threadIdx.x;
    if (i < N_NODES) { g_deg[i] = 1.0f; g_count[i] = 0; }  // self-loop weight = 1
}

__global__ void k_concat(const float4* __restrict__ cell, const float4* __restrict__ sub) {
    int i = blockIdx.x * blockDim.x + threadIdx.x;
    if (i >= NF4) return;
    float4 v = (i < CELL4) ? cell[i] : sub[i - CELL4];
    reinterpret_cast<float4*>(g_x0)[i] = v;
}

__global__ void k_degree(const int* __restrict__ ei, const float* __restrict__ ew) {
    int e = blockIdx.x * blockDim.x + threadIdx.x;
    if (e >= E_TOT) return;
    int c = ei[E_TOT + e];             // target (col)
    atomicAdd(&g_deg[c], ew[e]);
    atomicAdd(&g_count[c], 1);
}

__global__ void k_dinv() {
    int i = blockIdx.x * blockDim.x + threadIdx.x;
    if (i < N_NODES) g_dinv[i] = rsqrtf(g_deg[i]);   // deg >= 1 always
}

// single-block exclusive scan of g_count -> g_colptr / g_cursor
__global__ void k_scan() {
    __shared__ int sums[1024];
    int t = threadIdx.x;
    int base = t * 30;                 // 1024*30 = 30720 >= 30000
    int s = 0;
    for (int i = 0; i < 30; i++) {
        int idx = base + i;
        if (idx < N_NODES) s += g_count[idx];
    }
    sums[t] = s;
    __syncthreads();
    for (int off = 1; off < 1024; off <<= 1) {
        int v = (t >= off) ? sums[t - off] : 0;
        __syncthreads();
        sums[t] += v;
        __syncthreads();
    }
    int run = (t == 0) ? 0 : sums[t - 1];
    for (int i = 0; i < 30; i++) {
        int idx = base + i;
        if (idx < N_NODES) {
            g_colptr[idx] = run;
            g_cursor[idx] = run;
            run += g_count[idx];
        }
    }
    if (t == 1023) g_colptr[N_NODES] = E_TOT;
}

__global__ void k_scatter(const int* __restrict__ ei, const float* __restrict__ ew) {
    int e = blockIdx.x * blockDim.x + threadIdx.x;
    if (e >= E_TOT) return;
    int r = ei[e];
    int c = ei[E_TOT + e];
    int pos = atomicAdd(&g_cursor[c], 1);
    g_erow[pos]  = r;
    g_enorm[pos] = g_dinv[r] * ew[e] * g_dinv[c];
}

// ---------------- SpMM: one block per destination node ----------------
template <bool X0_TO_X1>
__global__ __launch_bounds__(256) void k_spmm() {
    const float* __restrict__ xin  = X0_TO_X1 ? g_x0 : g_x1;
    float*       __restrict__ xout = X0_TO_X1 ? g_x1 : g_x0;
    int i = blockIdx.x;
    int f = threadIdx.x;
    int beg = g_colptr[i];
    int end = g_colptr[i + 1];
    float di = g_dinv[i];
    float acc = di * di * xin[(size_t)i * FDIM + f];   // self-loop term
#pragma unroll 4
    for (int e = beg; e < end; e++) {
        int   r = g_erow[e];
        float w = g_enorm[e];
        acc += w * xin[(size_t)r * FDIM + f];
    }
    xout[(size_t)i * FDIM + f] = acc;
}

// ---------------- GEMM: C = A @ W^T + bias ; A = g_x1 [N,256], out -> g_x0 ----
#define BM 64
#define BN 64
#define BK 16
__global__ __launch_bounds__(256) void k_gemm(const float* __restrict__ W,
                                              const float* __restrict__ bias) {
    __shared__ float As[BK][BM + 4];   // row stride 68 floats = 272B (16B-aligned)
    __shared__ float Bs[BK][BN + 4];
    const float* __restrict__ A = g_x1;
    float* __restrict__ C = g_x0;

    int bm = blockIdx.x * BM;
    int bn = blockIdx.y * BN;
    int t  = threadIdx.x;
    int tm = t >> 4;            // 0..15
    int tn = t & 15;            // 0..15
    int lm = t >> 2;            // 0..63
    int lk = (t & 3) << 2;      // 0,4,8,12

    float acc[4][4];
#pragma unroll
    for (int i = 0; i < 4; i++)
#pragma unroll
        for (int j = 0; j < 4; j++) acc[i][j] = 0.f;

    int gm = bm + lm;
    const float* Aptr = A + (size_t)gm * FDIM;
    const float* Wptr = W + (size_t)(bn + lm) * FDIM;

    for (int k0 = 0; k0 < FDIM; k0 += BK) {
        float4 av = make_float4(0.f, 0.f, 0.f, 0.f);
        if (gm < N_NODES)
            av = *reinterpret_cast<const float4*>(Aptr + k0 + lk);
        float4 bv = *reinterpret_cast<const float4*>(Wptr + k0 + lk);
        As[lk + 0][lm] = av.x; As[lk + 1][lm] = av.y;
        As[lk + 2][lm] = av.z; As[lk + 3][lm] = av.w;
        Bs[lk + 0][lm] = bv.x; Bs[lk + 1][lm] = bv.y;
        Bs[lk + 2][lm] = bv.z; Bs[lk + 3][lm] = bv.w;
        __syncthreads();
#pragma unroll
        for (int kk = 0; kk < BK; kk++) {
            float4 a = *reinterpret_cast<const float4*>(&As[kk][tm * 4]);
            float4 b = *reinterpret_cast<const float4*>(&Bs[kk][tn * 4]);
            acc[0][0] += a.x * b.x; acc[0][1] += a.x * b.y; acc[0][2] += a.x * b.z; acc[0][3] += a.x * b.w;
            acc[1][0] += a.y * b.x; acc[1][1] += a.y * b.y; acc[1][2] += a.y * b.z; acc[1][3] += a.y * b.w;
            acc[2][0] += a.z * b.x; acc[2][1] += a.z * b.y; acc[2][2] += a.z * b.z; acc[2][3] += a.z * b.w;
            acc[3][0] += a.w * b.x; acc[3][1] += a.w * b.y; acc[3][2] += a.w * b.z; acc[3][3] += a.w * b.w;
        }
        __syncthreads();
    }

    int n0 = bn + tn * 4;
    float4 bb = *reinterpret_cast<const float4*>(&bias[n0]);
#pragma unroll
    for (int i = 0; i < 4; i++) {
        int m = bm + tm * 4 + i;
        if (m < N_NODES) {
            float4 v = make_float4(acc[i][0] + bb.x, acc[i][1] + bb.y,
                                   acc[i][2] + bb.z, acc[i][3] + bb.w);
            *reinterpret_cast<float4*>(&C[(size_t)m * FDIM + n0]) = v;
        }
    }
}

// ---------------- PReLU (in-place on g_x0) + BN partial stats ----------------
__global__ __launch_bounds__(256) void k_prelu_stats(const float* __restrict__ pw) {
    int b = blockIdx.x;
    int f = threadIdx.x;
    float w = pw[f];
    float s = 0.f, s2 = 0.f;
    int r0 = b * ROWS_PER;
    int r1 = r0 + ROWS_PER;
    for (int r = r0; r < r1; r++) {
        float v = g_x0[(size_t)r * FDIM + f];
        v = (v >= 0.f) ? v : w * v;
        g_x0[(size_t)r * FDIM + f] = v;
        s  += v;
        s2 += v * v;
    }
    g_part1[b * FDIM + f] = s;
    g_part2[b * FDIM + f] = s2;
}

__global__ void k_bn_finalize(const float* __restrict__ gamma,
                              const float* __restrict__ beta) {
    int f = threadIdx.x;   // 256 threads, 1 block — deterministic reduce order
    float s = 0.f, s2 = 0.f;
    for (int b = 0; b < NB_STAT; b++) {
        s  += g_part1[b * FDIM + f];
        s2 += g_part2[b * FDIM + f];
    }
    float inv_n = 1.0f / (float)N_NODES;
    float mean = s * inv_n;
    float var  = s2 * inv_n - mean * mean;
    float sc   = gamma[f] * rsqrtf(var + BN_EPS);
    g_scale[f] = sc;
    g_shift[f] = beta[f] - mean * sc;
}

template <bool FINAL>
__global__ void k_bn_apply(float* __restrict__ out_ext) {
    int i = blockIdx.x * blockDim.x + threadIdx.x;
    if (i >= NF4) return;
    int f4 = (i & 63) << 2;  // F/4 = 64 float4 groups per row
    float4 v  = reinterpret_cast<const float4*>(g_x0)[i];
    float4 sc = *reinterpret_cast<const float4*>(&g_scale[f4]);
    float4 sh = *reinterpret_cast<const float4*>(&g_shift[f4]);
    v.x = v.x * sc.x + sh.x;
    v.y = v.y * sc.y + sh.y;
    v.z = v.z * sc.z + sh.z;
    v.w = v.w * sc.w + sh.w;
    if (FINAL) reinterpret_cast<float4*>(out_ext)[i] = v;
    else       reinterpret_cast<float4*>(g_x0)[i]    = v;
}

// ---------------- launch ----------------
extern "C" void kernel_launch(void* const* d_in, const int* in_sizes, int n_in,
                              void* d_out, int out_size) {
    const float* cell  = (const float*)d_in[0];
    const float* sub   = (const float*)d_in[1];
    const int*   ei    = (const int*)  d_in[2];
    const float* ew    = (const float*)d_in[3];
    const float* W1    = (const float*)d_in[4];
    const float* b1    = (const float*)d_in[5];
    const float* W2    = (const float*)d_in[6];
    const float* b2    = (const float*)d_in[7];
    const float* pw    = (const float*)d_in[8];
    const float* gamma = (const float*)d_in[9];
    const float* beta  = (const float*)d_in[10];
    float* out = (float*)d_out;

    const int T = 256;
    // graph normalization setup (recomputed each call — deterministic work)
    k_init<<<(N_NODES + T - 1) / T, T>>>();
    k_concat<<<(NF4 + T - 1) / T, T>>>((const float4*)cell, (const float4*)sub);
    k_degree<<<(E_TOT + T - 1) / T, T>>>(ei, ew);
    k_dinv<<<(N_NODES + T - 1) / T, T>>>();
    k_scan<<<1, 1024>>>();
    k_scatter<<<(E_TOT + T - 1) / T, T>>>(ei, ew);

    dim3 gemm_grid((N_NODES + BM - 1) / BM, FDIM / BN);

    // ---- layer 1 ----
    k_spmm<true ><<<N_NODES, T>>>();   // x0 -> x1
    k_spmm<false><<<N_NODES, T>>>();   // x1 -> x0
    k_spmm<true ><<<N_NODES, T>>>();   // x0 -> x1
    k_gemm<<<gemm_grid, T>>>(W1, b1);  // x1 -> x0
    k_prelu_stats<<<NB_STAT, T>>>(pw);
    k_bn_finalize<<<1, FDIM>>>(gamma, beta);
    k_bn_apply<false><<<(NF4 + T - 1) / T, T>>>(nullptr);   // in-place x0

    // ---- layer 2 ----
    k_spmm<true ><<<N_NODES, T>>>();
    k_spmm<false><<<N_NODES, T>>>();
    k_spmm<true ><<<N_NODES, T>>>();
    k_gemm<<<gemm_grid, T>>>(W2, b2);
    k_prelu_stats<<<NB_STAT, T>>>(pw);
    k_bn_finalize<<<1, FDIM>>>(gamma, beta);
    k_bn_apply<true><<<(NF4 + T - 1) / T, T>>>(out);        // x0 -> d_out
}